// round 1
// baseline (speedup 1.0000x reference)
#include <cuda_runtime.h>
#include <math.h>

// ---------------- static problem constants ----------------
#define BGR 4
#define NN  40962
#define DEG 6
#define E0C (BGR * NN * DEG)          // 983052
#define M0  (BGR * NN)                // 163848

static const int NIN[4] = {40962, 20481, 10241, 5121};   // nodes/graph entering layer i
static const int KK [4] = {20481, 10241,  5121, 2561};   // kept/graph after pool i
static const int FOV[4] = {32, 64, 128, 128};

// ---------------- device scratch (static, no allocation) ----------------
__device__ float    g_H  [5243392];     // max M*Fo  (layer3: 40964*128)
__device__ float    g_XB [5243392];
__device__ float    g_XA [2621952];     // max pooled M*Fo (pool3: 20484*128)
__device__ float    g_deg[M0];
__device__ float    g_score[M0];
__device__ unsigned g_key[M0];
__device__ int      g_perm[BGR * 20481];
__device__ int      g_remap[M0];
__device__ int      g_srcbuf[2 * E0C];
__device__ int      g_dstbuf[2 * E0C];
__device__ int      g_ecnt[2];
__device__ int      g_E0cnt = E0C;      // static full-edge count for layer 0
__device__ unsigned g_hist[BGR * 256];
__device__ unsigned g_prefix[BGR];
__device__ int      g_want[BGR];
__device__ unsigned g_thresh[BGR];
__device__ int      g_allow[BGR];
__device__ int      g_cntKeep[BGR];
__device__ int      g_cntEq[BGR];
__device__ float    g_pinv;

// ---------------- kernels ----------------
__global__ void k_zero_f(float* p, int n) {
    int i = blockIdx.x * blockDim.x + threadIdx.x;
    if (i < n) p[i] = 0.f;
}

template <int FI, int FO>
__global__ void k_matmul(const float* __restrict__ X, const float* __restrict__ W,
                         float* __restrict__ H, int M) {
    int idx = blockIdx.x * blockDim.x + threadIdx.x;
    if (idx >= M * FO) return;
    int m = idx / FO, f = idx % FO;
    const float* xr = X + m * FI;
    float acc = 0.f;
#pragma unroll
    for (int k = 0; k < FI; k++) acc += xr[k] * W[k * FO + f];
    H[idx] = acc;
}

__global__ void k_deg(const int* __restrict__ dst, const int* __restrict__ ecnt,
                      float* __restrict__ deg) {
    int e = blockIdx.x * blockDim.x + threadIdx.x;
    if (e < *ecnt) atomicAdd(&deg[dst[e]], 1.0f);
}

template <int FO>
__global__ void k_agg(const int* __restrict__ src, const int* __restrict__ dst,
                      const int* __restrict__ ecnt, const float* __restrict__ H,
                      const float* __restrict__ deg, float* __restrict__ XB) {
    int gt = blockIdx.x * blockDim.x + threadIdx.x;
    int e = gt >> 5;
    if (e >= *ecnt) return;
    int lane = gt & 31;
    int s = src[e], d = dst[e];
    float norm = rsqrtf(deg[s] + 1.f) * rsqrtf(deg[d] + 1.f);
    const float* hr = H + s * FO;
    float* xr = XB + d * FO;
#pragma unroll
    for (int f = lane; f < FO; f += 32) atomicAdd(&xr[f], hr[f] * norm);
}

template <int FO>
__global__ void k_fin(float* __restrict__ XB, const float* __restrict__ H,
                      const float* __restrict__ deg, const float* __restrict__ b, int M) {
    int idx = blockIdx.x * blockDim.x + threadIdx.x;
    if (idx >= M * FO) return;
    int m = idx / FO, f = idx % FO;
    float v = XB[idx] + H[idx] / (deg[m] + 1.f) + b[f];
    XB[idx] = v > 0.f ? v : 0.f;
}

__global__ void k_pnorm(const float* __restrict__ p, int Fo, float* __restrict__ out) {
    __shared__ float sh[128];
    float v = (threadIdx.x < (unsigned)Fo) ? p[threadIdx.x] : 0.f;
    sh[threadIdx.x] = v * v;
    __syncthreads();
    for (int s = 64; s > 0; s >>= 1) {
        if ((int)threadIdx.x < s) sh[threadIdx.x] += sh[threadIdx.x + s];
        __syncthreads();
    }
    if (threadIdx.x == 0) *out = rsqrtf(sh[0]);
}

template <int FO>
__global__ void k_score(const float* __restrict__ XB, const float* __restrict__ p, int M,
                        float* __restrict__ score, unsigned* __restrict__ key) {
    int gt = blockIdx.x * blockDim.x + threadIdx.x;
    int m = gt >> 5;
    if (m >= M) return;
    int lane = gt & 31;
    float acc = 0.f;
#pragma unroll
    for (int f = lane; f < FO; f += 32) acc += XB[m * FO + f] * p[f];
#pragma unroll
    for (int o = 16; o; o >>= 1) acc += __shfl_down_sync(0xffffffffu, acc, o);
    if (lane == 0) {
        score[m] = acc;
        unsigned u = __float_as_uint(acc);
        key[m] = (u & 0x80000000u) ? ~u : (u | 0x80000000u);
    }
}

__global__ void k_init(int M, int k, int* __restrict__ remap, unsigned* __restrict__ hist,
                       unsigned* __restrict__ prefix, int* __restrict__ want,
                       int* __restrict__ cntK, int* __restrict__ cntE, int* __restrict__ ecntN) {
    int i = blockIdx.x * blockDim.x + threadIdx.x;
    if (i < M) remap[i] = -1;
    if (blockIdx.x == 0) {
        for (int j = threadIdx.x; j < BGR * 256; j += blockDim.x) hist[j] = 0u;
        if (threadIdx.x < BGR) {
            prefix[threadIdx.x] = 0u;
            want[threadIdx.x] = k;
            cntK[threadIdx.x] = 0;
            cntE[threadIdx.x] = 0;
        }
        if (threadIdx.x == 0) *ecntN = 0;
    }
}

__global__ void k_hist(const unsigned* __restrict__ key, int M, int n, int pass,
                       const unsigned* __restrict__ prefix, unsigned* __restrict__ hist) {
    __shared__ unsigned sh[BGR * 256];
    for (int j = threadIdx.x; j < BGR * 256; j += blockDim.x) sh[j] = 0u;
    __syncthreads();
    int m = blockIdx.x * blockDim.x + threadIdx.x;
    if (m < M) {
        unsigned kk = key[m];
        int b = m / n;
        bool ok = (pass == 0) || ((kk >> (32 - 8 * pass)) == prefix[b]);
        if (ok) {
            unsigned d = (kk >> (24 - 8 * pass)) & 255u;
            atomicAdd(&sh[b * 256 + d], 1u);
        }
    }
    __syncthreads();
    for (int j = threadIdx.x; j < BGR * 256; j += blockDim.x) {
        unsigned v = sh[j];
        if (v) atomicAdd(&hist[j], v);
    }
}

__global__ void k_scan(int pass, unsigned* __restrict__ hist, unsigned* __restrict__ prefix,
                       int* __restrict__ want, unsigned* __restrict__ thresh,
                       int* __restrict__ allow) {
    int b = threadIdx.x;
    if (b < BGR) {
        int w = want[b];
        unsigned cum = 0;
        int d = 255;
        for (; d >= 0; d--) {
            unsigned h = hist[b * 256 + d];
            if (cum + h >= (unsigned)w) break;
            cum += h;
        }
        if (d < 0) d = 0;
        prefix[b] = (prefix[b] << 8) | (unsigned)d;
        want[b] = w - (int)cum;
        if (pass == 3) {
            thresh[b] = prefix[b];
            allow[b] = w - (int)cum;
        }
    }
    __syncthreads();
    for (int j = threadIdx.x; j < BGR * 256; j += blockDim.x) hist[j] = 0u;
}

__global__ void k_compact(const unsigned* __restrict__ key, int M, int n, int k,
                          const unsigned* __restrict__ thresh, const int* __restrict__ allow,
                          int* __restrict__ cntK, int* __restrict__ cntE,
                          int* __restrict__ perm, int* __restrict__ remap) {
    int m = blockIdx.x * blockDim.x + threadIdx.x;
    if (m >= M) return;
    unsigned kk = key[m];
    int b = m / n;
    unsigned t = thresh[b];
    bool keep = false;
    if (kk > t) keep = true;
    else if (kk == t) {
        if (atomicAdd(&cntE[b], 1) < allow[b]) keep = true;
    }
    if (keep) {
        int pos = atomicAdd(&cntK[b], 1);
        int nid = b * k + pos;
        perm[nid] = m;
        remap[m] = nid;
    }
}

template <int FO>
__global__ void k_gather(const float* __restrict__ XB, const int* __restrict__ perm,
                         const float* __restrict__ score, const float* __restrict__ pinv,
                         float* __restrict__ XA, int Mnew) {
    int idx = blockIdx.x * blockDim.x + threadIdx.x;
    if (idx >= Mnew * FO) return;
    int j = idx / FO, f = idx % FO;
    int m = perm[j];
    XA[idx] = XB[m * FO + f] * tanhf(score[m] * (*pinv));
}

__global__ void k_eremap(const int* __restrict__ srcO, const int* __restrict__ dstO,
                         const int* __restrict__ ecntO, const int* __restrict__ remap,
                         int* __restrict__ srcN, int* __restrict__ dstN, int* __restrict__ ecntN) {
    int e = blockIdx.x * blockDim.x + threadIdx.x;
    if (e >= *ecntO) return;
    int s = remap[srcO[e]], d = remap[dstO[e]];
    if (s >= 0 && d >= 0) {
        int pos = atomicAdd(ecntN, 1);
        srcN[pos] = s;
        dstN[pos] = d;
    }
}

__global__ void k_readout(const float* __restrict__ X, const float* __restrict__ meta,
                          const float* __restrict__ cw, const float* __restrict__ cb,
                          const float* __restrict__ fcw, const float* __restrict__ fcb,
                          const float* __restrict__ fc2w, const float* __restrict__ fc2b,
                          float* __restrict__ out, int kn) {
    __shared__ float v[260];
    __shared__ float red[128];
    int b = blockIdx.x, f = threadIdx.x;   // 128 threads
    float mx = -3.4e38f, sm = 0.f;
    const float* base = X + (size_t)b * kn * 128 + f;
    for (int i = 0; i < kn; i++) {
        float val = base[(size_t)i * 128];
        mx = fmaxf(mx, val);
        sm += val;
    }
    v[f] = mx;
    v[128 + f] = sm / (float)kn;
    if (f < 4) {
        float mv = meta[b] * cw[f] + cb[f];
        v[256 + f] = mv > 0.f ? mv : 0.f;
    }
    __syncthreads();
    float acc = fcb[f];
    for (int i = 0; i < 260; i++) acc += v[i] * fcw[i * 128 + f];
    float hv = acc > 0.f ? acc : 0.f;
    red[f] = hv * fc2w[f];
    __syncthreads();
    for (int s = 64; s > 0; s >>= 1) {
        if (f < s) red[f] += red[f + s];
        __syncthreads();
    }
    if (f == 0) out[b] = red[0] + fc2b[0];
}

// ---------------- host orchestration ----------------
static inline int gdiv(int n, int t) { return (n + t - 1) / t; }

extern "C" void kernel_launch(void* const* d_in, const int* in_sizes, int n_in,
                              void* d_out, int out_size) {
    const float* x0   = (const float*)d_in[0];
    const int*   ei   = (const int*)  d_in[1];
    const float* meta = (const float*)d_in[2];
    const float* W[4]  = {(const float*)d_in[3], (const float*)d_in[6],
                          (const float*)d_in[9], (const float*)d_in[12]};
    const float* bb[4] = {(const float*)d_in[4], (const float*)d_in[7],
                          (const float*)d_in[10], (const float*)d_in[13]};
    const float* pp[4] = {(const float*)d_in[5], (const float*)d_in[8],
                          (const float*)d_in[11], (const float*)d_in[14]};
    const float* cw   = (const float*)d_in[15];
    const float* cb   = (const float*)d_in[16];
    const float* fcw  = (const float*)d_in[17];
    const float* fcb  = (const float*)d_in[18];
    const float* fc2w = (const float*)d_in[19];
    const float* fc2b = (const float*)d_in[20];
    float* out = (float*)d_out;

    float *H, *XB, *XA, *deg, *score, *pinv;
    unsigned *key, *hist, *prefix, *thresh;
    int *perm, *remap, *want, *allow, *cntK, *cntE, *srcb, *dstb, *ecnt, *e0c;
    cudaGetSymbolAddress((void**)&H, g_H);
    cudaGetSymbolAddress((void**)&XB, g_XB);
    cudaGetSymbolAddress((void**)&XA, g_XA);
    cudaGetSymbolAddress((void**)&deg, g_deg);
    cudaGetSymbolAddress((void**)&score, g_score);
    cudaGetSymbolAddress((void**)&key, g_key);
    cudaGetSymbolAddress((void**)&perm, g_perm);
    cudaGetSymbolAddress((void**)&remap, g_remap);
    cudaGetSymbolAddress((void**)&srcb, g_srcbuf);
    cudaGetSymbolAddress((void**)&dstb, g_dstbuf);
    cudaGetSymbolAddress((void**)&ecnt, g_ecnt);
    cudaGetSymbolAddress((void**)&e0c, g_E0cnt);
    cudaGetSymbolAddress((void**)&hist, g_hist);
    cudaGetSymbolAddress((void**)&prefix, g_prefix);
    cudaGetSymbolAddress((void**)&want, g_want);
    cudaGetSymbolAddress((void**)&thresh, g_thresh);
    cudaGetSymbolAddress((void**)&allow, g_allow);
    cudaGetSymbolAddress((void**)&cntK, g_cntKeep);
    cudaGetSymbolAddress((void**)&cntE, g_cntEq);
    cudaGetSymbolAddress((void**)&pinv, g_pinv);

    const int T = 256;

    for (int i = 0; i < 4; i++) {
        int n = NIN[i], M = BGR * n, k = KK[i], Fo = FOV[i];
        const float* Xin = i ? XA : x0;
        const int* eS = i ? (srcb + ((i + 1) & 1) * E0C) : ei;
        const int* eD = i ? (dstb + ((i + 1) & 1) * E0C) : (ei + E0C);
        const int* eC = i ? (ecnt + ((i + 1) & 1)) : e0c;
        int* eSn = srcb + (i & 1) * E0C;
        int* eDn = dstb + (i & 1) * E0C;
        int* eCn = ecnt + (i & 1);

        // 1. H = X @ W
        switch (i) {
            case 0: k_matmul<4, 32>  <<<gdiv(M * 32, T), T>>>(Xin, W[0], H, M); break;
            case 1: k_matmul<32, 64> <<<gdiv(M * 64, T), T>>>(Xin, W[1], H, M); break;
            case 2: k_matmul<64, 128><<<gdiv(M * 128, T), T>>>(Xin, W[2], H, M); break;
            case 3: k_matmul<128,128><<<gdiv(M * 128, T), T>>>(Xin, W[3], H, M); break;
        }
        // 2-3. degree
        k_zero_f<<<gdiv(M, T), T>>>(deg, M);
        k_deg<<<gdiv(E0C, T), T>>>(eD, eC, deg);
        // 4-5. aggregate
        k_zero_f<<<gdiv(M * Fo, T), T>>>(XB, M * Fo);
        switch (Fo) {
            case 32:  k_agg<32> <<<gdiv(E0C * 32, T), T>>>(eS, eD, eC, H, deg, XB); break;
            case 64:  k_agg<64> <<<gdiv(E0C * 32, T), T>>>(eS, eD, eC, H, deg, XB); break;
            case 128: k_agg<128><<<gdiv(E0C * 32, T), T>>>(eS, eD, eC, H, deg, XB); break;
        }
        // 6. finalize + relu
        switch (Fo) {
            case 32:  k_fin<32> <<<gdiv(M * Fo, T), T>>>(XB, H, deg, bb[i], M); break;
            case 64:  k_fin<64> <<<gdiv(M * Fo, T), T>>>(XB, H, deg, bb[i], M); break;
            case 128: k_fin<128><<<gdiv(M * Fo, T), T>>>(XB, H, deg, bb[i], M); break;
        }
        // 7. scores + keys
        k_pnorm<<<1, 128>>>(pp[i], Fo, pinv);
        switch (Fo) {
            case 32:  k_score<32> <<<gdiv(M * 32, T), T>>>(XB, pp[i], M, score, key); break;
            case 64:  k_score<64> <<<gdiv(M * 32, T), T>>>(XB, pp[i], M, score, key); break;
            case 128: k_score<128><<<gdiv(M * 32, T), T>>>(XB, pp[i], M, score, key); break;
        }
        // 8. radix select (exact k-th largest key)
        k_init<<<gdiv(M, T), T>>>(M, k, remap, hist, prefix, want, cntK, cntE, eCn);
        for (int p = 0; p < 4; p++) {
            k_hist<<<gdiv(M, T), T>>>(key, M, n, p, prefix, hist);
            k_scan<<<1, 256>>>(p, hist, prefix, want, thresh, allow);
        }
        // 9. compact kept nodes
        k_compact<<<gdiv(M, T), T>>>(key, M, n, k, thresh, allow, cntK, cntE, perm, remap);
        // 10. gather + tanh scale
        switch (Fo) {
            case 32:  k_gather<32> <<<gdiv(BGR * k * Fo, T), T>>>(XB, perm, score, pinv, XA, BGR * k); break;
            case 64:  k_gather<64> <<<gdiv(BGR * k * Fo, T), T>>>(XB, perm, score, pinv, XA, BGR * k); break;
            case 128: k_gather<128><<<gdiv(BGR * k * Fo, T), T>>>(XB, perm, score, pinv, XA, BGR * k); break;
        }
        // 11. edge remap + compaction (not needed after last pool)
        if (i < 3)
            k_eremap<<<gdiv(E0C, T), T>>>(eS, eD, eC, remap, eSn, eDn, eCn);
    }

    // readout: max/mean pool + metadata conv + fc + fc2
    k_readout<<<BGR, 128>>>(XA, meta, cw, cb, fcw, fcb, fc2w, fc2b, out, KK[3]);
    (void)in_sizes; (void)n_in; (void)out_size;
}

// round 2
// speedup vs baseline: 1.7875x; 1.7875x over previous
#include <cuda_runtime.h>
#include <math.h>

// ---------------- static problem constants ----------------
#define BGR 4
#define NN  40962
#define DEG 6
#define E0C (BGR * NN * DEG)          // 983052
#define M0  (BGR * NN)                // 163848

static const int NIN[4] = {40962, 20481, 10241, 5121};   // nodes/graph entering layer i
static const int KK [4] = {20481, 10241,  5121, 2561};   // kept/graph after pool i

// ---------------- device scratch (static, no allocation) ----------------
__device__ float    g_H  [5243392];
__device__ float    g_XB [5243392];
__device__ float    g_XA [2621952];
__device__ float    g_deg[M0];
__device__ float    g_score[M0];
__device__ unsigned g_key[M0];
__device__ int      g_remap[M0];
__device__ int      g_srcbuf[2 * E0C];
__device__ int      g_dstbuf[2 * E0C];
__device__ int      g_ecnt[2];
__device__ int      g_E0cnt = E0C;
__device__ unsigned g_thresh[BGR];
__device__ int      g_allow[BGR];
__device__ int      g_cntKeep[BGR];
__device__ int      g_cntEq[BGR];
__device__ float    g_pinv[4];
__device__ float    g_pmax[32 * 128];
__device__ float    g_psum[32 * 128];

// ---------------- helpers ----------------
__device__ __forceinline__ unsigned long long pack2(float a, float b) {
    unsigned long long r;
    asm("mov.b64 %0,{%1,%2};" : "=l"(r) : "f"(a), "f"(b));
    return r;
}
__device__ __forceinline__ void unpack2(unsigned long long v, float& a, float& b) {
    asm("mov.b64 {%0,%1},%2;" : "=f"(a), "=f"(b) : "l"(v));
}
__device__ __forceinline__ void ffma2(unsigned long long& acc, unsigned long long x,
                                      unsigned long long w) {
    asm("fma.rn.f32x2 %0,%1,%2,%0;" : "+l"(acc) : "l"(x), "l"(w));
}

// ---------------- kernels ----------------
// prep: zero layer-0 deg, compute pinv[4] = 1/||p_i||
__global__ void k_prep(const float* __restrict__ p1, const float* __restrict__ p2,
                       const float* __restrict__ p3, const float* __restrict__ p4,
                       float* __restrict__ pinv, float* __restrict__ deg) {
    int gt = blockIdx.x * blockDim.x + threadIdx.x;
    for (int i = gt; i < M0; i += gridDim.x * blockDim.x) deg[i] = 0.f;
    if (blockIdx.x < 4 && threadIdx.x < 32) {
        const float* p = (blockIdx.x == 0) ? p1 : (blockIdx.x == 1) ? p2
                         : (blockIdx.x == 2) ? p3 : p4;
        int len = (blockIdx.x == 0) ? 32 : (blockIdx.x == 1) ? 64 : 128;
        float acc = 0.f;
        for (int f = threadIdx.x; f < len; f += 32) { float v = p[f]; acc += v * v; }
#pragma unroll
        for (int o = 16; o; o >>= 1) acc += __shfl_down_sync(0xffffffffu, acc, o);
        if (threadIdx.x == 0) pinv[blockIdx.x] = rsqrtf(acc);
    }
}

__global__ void k_deg0(const int* __restrict__ dst, float* __restrict__ deg) {
    int e = blockIdx.x * blockDim.x + threadIdx.x;
    if (e < E0C) atomicAdd(&deg[dst[e]], 1.0f);
}

// fused matmul: H = X@W,  XB = H/(deg+1) + b   (4 outputs/thread, f32x2 FFMA)
template <int FI, int FO>
__global__ void k_mm(const float* __restrict__ X, const float* __restrict__ W,
                     const float* __restrict__ bias, const float* __restrict__ deg,
                     float* __restrict__ H, float* __restrict__ XB, int M) {
    constexpr int J = FO / 4;
    int idx = blockIdx.x * blockDim.x + threadIdx.x;
    if (idx >= M * J) return;
    int m = idx / J, j = (idx % J) * 4;
    const float* xr = X + m * FI;
    unsigned long long acc0 = 0ull, acc1 = 0ull;
#pragma unroll
    for (int kq = 0; kq < FI; kq++) {
        float xv = xr[kq];
        unsigned long long xx = pack2(xv, xv);
        ulonglong2 wv = *(const ulonglong2*)(W + kq * FO + j);
        ffma2(acc0, xx, wv.x);
        ffma2(acc1, xx, wv.y);
    }
    float a0, a1, a2, a3;
    unpack2(acc0, a0, a1);
    unpack2(acc1, a2, a3);
    float invd = 1.0f / (deg[m] + 1.0f);
    float4 bv = *(const float4*)(bias + j);
    *(float4*)(H + m * FO + j) = make_float4(a0, a1, a2, a3);
    *(float4*)(XB + m * FO + j) =
        make_float4(a0 * invd + bv.x, a1 * invd + bv.y, a2 * invd + bv.z, a3 * invd + bv.w);
}

// edge aggregation: warp per edge, grid-stride
template <int FO>
__global__ void k_agg(const int* __restrict__ src, const int* __restrict__ dst,
                      const int* __restrict__ ecnt, const float* __restrict__ H,
                      const float* __restrict__ deg, float* __restrict__ XB) {
    int E = *ecnt;
    int gw = (blockIdx.x * blockDim.x + threadIdx.x) >> 5;
    int lane = threadIdx.x & 31;
    int stride = (gridDim.x * blockDim.x) >> 5;
    for (int e = gw; e < E; e += stride) {
        int s = src[e], d = dst[e];
        float norm = rsqrtf(deg[s] + 1.f) * rsqrtf(deg[d] + 1.f);
        const float* hr = H + s * FO;
        float* xr = XB + d * FO;
#pragma unroll
        for (int f = lane; f < FO; f += 32) atomicAdd(&xr[f], hr[f] * norm);
    }
}

// fused relu(in place) + score + monotonic key
template <int FO>
__global__ void k_score(float* __restrict__ XB, const float* __restrict__ p, int M,
                        float* __restrict__ score, unsigned* __restrict__ key) {
    int gw = (blockIdx.x * blockDim.x + threadIdx.x) >> 5;
    int lane = threadIdx.x & 31;
    int stride = (gridDim.x * blockDim.x) >> 5;
    for (int m = gw; m < M; m += stride) {
        float acc = 0.f;
#pragma unroll
        for (int f = lane; f < FO; f += 32) {
            float v = XB[m * FO + f];
            v = fmaxf(v, 0.f);
            XB[m * FO + f] = v;
            acc += v * p[f];
        }
#pragma unroll
        for (int o = 16; o; o >>= 1) acc += __shfl_down_sync(0xffffffffu, acc, o);
        if (lane == 0) {
            score[m] = acc;
            unsigned u = __float_as_uint(acc);
            key[m] = (u & 0x80000000u) ? ~u : (u | 0x80000000u);
        }
    }
}

// single-kernel 4-pass radix select (1 block per graph); also zeroes counters,
// next-layer deg, and next-layer edge count
__global__ void k_select(const unsigned* __restrict__ key, int n, int k,
                         unsigned* __restrict__ thresh, int* __restrict__ allow,
                         int* __restrict__ cntK, int* __restrict__ cntE,
                         float* __restrict__ degN, int MN, int* __restrict__ eCn) {
    __shared__ unsigned hist[256];
    __shared__ unsigned sP;
    __shared__ int sW;
    int b = blockIdx.x;
    const unsigned* kb = key + b * n;
    unsigned prefix = 0;
    int want = k;
    for (int pass = 0; pass < 4; pass++) {
        for (int i = threadIdx.x; i < 256; i += blockDim.x) hist[i] = 0u;
        __syncthreads();
        int shp = 32 - 8 * pass, shd = 24 - 8 * pass;
        for (int i = threadIdx.x; i < n; i += blockDim.x) {
            unsigned kk = kb[i];
            if (pass == 0 || (kk >> shp) == prefix)
                atomicAdd(&hist[(kk >> shd) & 255u], 1u);
        }
        __syncthreads();
        if (threadIdx.x == 0) {
            unsigned cum = 0;
            int d = 255;
            for (;;) {
                unsigned h = hist[d];
                if (cum + h >= (unsigned)want || d == 0) break;
                cum += h;
                d--;
            }
            sP = (prefix << 8) | (unsigned)d;
            sW = want - (int)cum;
        }
        __syncthreads();
        prefix = sP;
        want = sW;
    }
    if (threadIdx.x == 0) {
        thresh[b] = prefix;
        allow[b] = want;
        cntK[b] = 0;
        cntE[b] = 0;
        if (b == 0) *eCn = 0;
    }
    for (int i = b * blockDim.x + threadIdx.x; i < MN; i += gridDim.x * blockDim.x)
        degN[i] = 0.f;
}

// fused compact + gather: warp per old node, keeps top-k set, copies scaled row
template <int FO>
__global__ void k_cg(const unsigned* __restrict__ key, const float* __restrict__ score,
                     const float* __restrict__ XB, int M, int n, int k,
                     const unsigned* __restrict__ thresh, const int* __restrict__ allow,
                     int* __restrict__ cntK, int* __restrict__ cntE,
                     int* __restrict__ remap, const float* __restrict__ pinv,
                     float* __restrict__ XA) {
    int gw = (blockIdx.x * blockDim.x + threadIdx.x) >> 5;
    int lane = threadIdx.x & 31;
    int stride = (gridDim.x * blockDim.x) >> 5;
    for (int m = gw; m < M; m += stride) {
        int b = m / n;
        int nid = -1;
        if (lane == 0) {
            unsigned kk = key[m], t = thresh[b];
            bool keep = kk > t;
            if (!keep && kk == t) keep = (atomicAdd(&cntE[b], 1) < allow[b]);
            if (keep) nid = b * k + atomicAdd(&cntK[b], 1);
            remap[m] = nid;
        }
        nid = __shfl_sync(0xffffffffu, nid, 0);
        if (nid >= 0) {
            float t = tanhf(score[m] * (*pinv));
#pragma unroll
            for (int f = lane; f < FO; f += 32) XA[nid * FO + f] = XB[m * FO + f] * t;
        }
    }
}

// fused edge remap/compact + next-layer degree count
__global__ void k_eremap(const int* __restrict__ srcO, const int* __restrict__ dstO,
                         const int* __restrict__ ecntO, const int* __restrict__ remap,
                         int* __restrict__ srcN, int* __restrict__ dstN,
                         int* __restrict__ ecntN, float* __restrict__ degN) {
    int E = *ecntO;
    int gt = blockIdx.x * blockDim.x + threadIdx.x;
    int stride = gridDim.x * blockDim.x;
    for (int e = gt; e < E; e += stride) {
        int s = remap[srcO[e]], d = remap[dstO[e]];
        if (s >= 0 && d >= 0) {
            int pos = atomicAdd(ecntN, 1);
            srcN[pos] = s;
            dstN[pos] = d;
            atomicAdd(&degN[d], 1.f);
        }
    }
}

// readout part 1: partial max/sum over row slices (8 slices per graph)
__global__ void k_read1(const float* __restrict__ X, float* __restrict__ pmax,
                        float* __restrict__ psum, int kn) {
    int b = blockIdx.x >> 3, s = blockIdx.x & 7, f = threadIdx.x;   // 128 threads
    int per = (kn + 7) / 8;
    int i0 = s * per, i1 = min(kn, i0 + per);
    float mx = -3.4e38f, sm = 0.f;
    const float* base = X + (size_t)b * kn * 128 + f;
    for (int i = i0; i < i1; i++) {
        float v = base[(size_t)i * 128];
        mx = fmaxf(mx, v);
        sm += v;
    }
    pmax[blockIdx.x * 128 + f] = mx;
    psum[blockIdx.x * 128 + f] = sm;
}

// readout part 2: final reduce + metadata conv + fc + fc2
__global__ void k_read2(const float* __restrict__ pmax, const float* __restrict__ psum,
                        const float* __restrict__ meta, const float* __restrict__ cw,
                        const float* __restrict__ cb, const float* __restrict__ fcw,
                        const float* __restrict__ fcb, const float* __restrict__ fc2w,
                        const float* __restrict__ fc2b, float* __restrict__ out, int kn) {
    __shared__ float v[260];
    __shared__ float red[128];
    int b = blockIdx.x, f = threadIdx.x;   // 128 threads
    float mx = -3.4e38f, sm = 0.f;
#pragma unroll
    for (int s = 0; s < 8; s++) {
        mx = fmaxf(mx, pmax[(b * 8 + s) * 128 + f]);
        sm += psum[(b * 8 + s) * 128 + f];
    }
    v[f] = mx;
    v[128 + f] = sm / (float)kn;
    if (f < 4) {
        float mv = meta[b] * cw[f] + cb[f];
        v[256 + f] = mv > 0.f ? mv : 0.f;
    }
    __syncthreads();
    float acc = fcb[f];
    for (int i = 0; i < 260; i++) acc += v[i] * fcw[i * 128 + f];
    float hv = acc > 0.f ? acc : 0.f;
    red[f] = hv * fc2w[f];
    __syncthreads();
    for (int s = 64; s > 0; s >>= 1) {
        if (f < s) red[f] += red[f + s];
        __syncthreads();
    }
    if (f == 0) out[b] = red[0] + fc2b[0];
}

// ---------------- host orchestration ----------------
static inline int gdiv(int n, int t) { return (n + t - 1) / t; }

extern "C" void kernel_launch(void* const* d_in, const int* in_sizes, int n_in,
                              void* d_out, int out_size) {
    const float* x0   = (const float*)d_in[0];
    const int*   ei   = (const int*)  d_in[1];
    const float* meta = (const float*)d_in[2];
    const float* W[4]  = {(const float*)d_in[3], (const float*)d_in[6],
                          (const float*)d_in[9], (const float*)d_in[12]};
    const float* bb[4] = {(const float*)d_in[4], (const float*)d_in[7],
                          (const float*)d_in[10], (const float*)d_in[13]};
    const float* pp[4] = {(const float*)d_in[5], (const float*)d_in[8],
                          (const float*)d_in[11], (const float*)d_in[14]};
    const float* cw   = (const float*)d_in[15];
    const float* cb   = (const float*)d_in[16];
    const float* fcw  = (const float*)d_in[17];
    const float* fcb  = (const float*)d_in[18];
    const float* fc2w = (const float*)d_in[19];
    const float* fc2b = (const float*)d_in[20];
    float* out = (float*)d_out;

    float *H, *XB, *XA, *deg, *score, *pinv, *pmax, *psum;
    unsigned *key, *thresh;
    int *remap, *allow, *cntK, *cntE, *srcb, *dstb, *ecnt, *e0c;
    cudaGetSymbolAddress((void**)&H, g_H);
    cudaGetSymbolAddress((void**)&XB, g_XB);
    cudaGetSymbolAddress((void**)&XA, g_XA);
    cudaGetSymbolAddress((void**)&deg, g_deg);
    cudaGetSymbolAddress((void**)&score, g_score);
    cudaGetSymbolAddress((void**)&key, g_key);
    cudaGetSymbolAddress((void**)&remap, g_remap);
    cudaGetSymbolAddress((void**)&srcb, g_srcbuf);
    cudaGetSymbolAddress((void**)&dstb, g_dstbuf);
    cudaGetSymbolAddress((void**)&ecnt, g_ecnt);
    cudaGetSymbolAddress((void**)&e0c, g_E0cnt);
    cudaGetSymbolAddress((void**)&thresh, g_thresh);
    cudaGetSymbolAddress((void**)&allow, g_allow);
    cudaGetSymbolAddress((void**)&cntK, g_cntKeep);
    cudaGetSymbolAddress((void**)&cntE, g_cntEq);
    cudaGetSymbolAddress((void**)&pinv, g_pinv);
    cudaGetSymbolAddress((void**)&pmax, g_pmax);
    cudaGetSymbolAddress((void**)&psum, g_psum);

    const int T = 256;

    // prep: zero deg (layer 0) + compute all 4 pinv
    k_prep<<<256, T>>>(pp[0], pp[1], pp[2], pp[3], pinv, deg);
    // layer-0 degree count
    k_deg0<<<gdiv(E0C, T), T>>>(ei + E0C, deg);

    for (int i = 0; i < 4; i++) {
        int n = NIN[i], M = BGR * n, k = KK[i];
        const float* Xin = i ? XA : x0;
        const int* eS = i ? (srcb + ((i + 1) & 1) * E0C) : ei;
        const int* eD = i ? (dstb + ((i + 1) & 1) * E0C) : (ei + E0C);
        const int* eC = i ? (ecnt + ((i + 1) & 1)) : e0c;
        int* eSn = srcb + (i & 1) * E0C;
        int* eDn = dstb + (i & 1) * E0C;
        int* eCn = ecnt + (i & 1);

        // 1. H = X@W and XB = H/(deg+1)+b (fused)
        switch (i) {
            case 0: k_mm<4, 32>   <<<gdiv(M * 8,  T), T>>>(Xin, W[0], bb[0], deg, H, XB, M); break;
            case 1: k_mm<32, 64>  <<<gdiv(M * 16, T), T>>>(Xin, W[1], bb[1], deg, H, XB, M); break;
            case 2: k_mm<64, 128> <<<gdiv(M * 32, T), T>>>(Xin, W[2], bb[2], deg, H, XB, M); break;
            case 3: k_mm<128, 128><<<gdiv(M * 32, T), T>>>(Xin, W[3], bb[3], deg, H, XB, M); break;
        }
        // 2. aggregate (atomic scatter)
        int aggGrid = (i == 0) ? gdiv(E0C * 32, T) : 4096;
        switch (i) {
            case 0: k_agg<32> <<<aggGrid, T>>>(eS, eD, eC, H, deg, XB); break;
            case 1: k_agg<64> <<<aggGrid, T>>>(eS, eD, eC, H, deg, XB); break;
            case 2: k_agg<128><<<aggGrid, T>>>(eS, eD, eC, H, deg, XB); break;
            case 3: k_agg<128><<<aggGrid, T>>>(eS, eD, eC, H, deg, XB); break;
        }
        // 3. relu + score + key (fused)
        switch (i) {
            case 0: k_score<32> <<<gdiv(M * 32, T), T>>>(XB, pp[0], M, score, key); break;
            case 1: k_score<64> <<<gdiv(M * 32, T), T>>>(XB, pp[1], M, score, key); break;
            case 2: k_score<128><<<gdiv(M * 32, T), T>>>(XB, pp[2], M, score, key); break;
            case 3: k_score<128><<<gdiv(M * 32, T), T>>>(XB, pp[3], M, score, key); break;
        }
        // 4. radix select (single kernel) + zero counters/next deg/next ecnt
        int MN = (i < 3) ? BGR * k : 0;
        k_select<<<BGR, 1024>>>(key, n, k, thresh, allow, cntK, cntE, deg, MN, eCn);
        // 5. compact + gather (fused)
        switch (i) {
            case 0: k_cg<32> <<<gdiv(M * 32, T), T>>>(key, score, XB, M, n, k, thresh, allow,
                                                      cntK, cntE, remap, pinv + 0, XA); break;
            case 1: k_cg<64> <<<gdiv(M * 32, T), T>>>(key, score, XB, M, n, k, thresh, allow,
                                                      cntK, cntE, remap, pinv + 1, XA); break;
            case 2: k_cg<128><<<gdiv(M * 32, T), T>>>(key, score, XB, M, n, k, thresh, allow,
                                                      cntK, cntE, remap, pinv + 2, XA); break;
            case 3: k_cg<128><<<gdiv(M * 32, T), T>>>(key, score, XB, M, n, k, thresh, allow,
                                                      cntK, cntE, remap, pinv + 3, XA); break;
        }
        // 6. edge remap + next-layer degree (fused); not needed after last pool
        if (i < 3) {
            int erGrid = (i == 0) ? gdiv(E0C, T) : 2048;
            k_eremap<<<erGrid, T>>>(eS, eD, eC, remap, eSn, eDn, eCn, deg);
        }
    }

    // readout
    k_read1<<<BGR * 8, 128>>>(XA, pmax, psum, KK[3]);
    k_read2<<<BGR, 128>>>(pmax, psum, meta, cw, cb, fcw, fcb, fc2w, fc2b, out, KK[3]);
    (void)in_sizes; (void)n_in; (void)out_size;
}